// round 5
// baseline (speedup 1.0000x reference)
#include <cuda_runtime.h>
#include <cuda_bf16.h>
#include <cstdint>

// BCE-with-logits mean over 8192x8192, single kernel.
// Per-WARP dynamic chunk scheduling: no __syncthreads in the hot loop,
// warps fully decoupled; atomic work counter with prefetched grab.
// Last-block-done final reduction; counters self-reset for graph replay.

#define NBLOCKS    1184          // 148 SMs * 8 CTAs (one full wave)
#define NTHREADS   256
#define WCHUNK_IT  16                    // float4 per lane per chunk
#define WCHUNK     (32 * WCHUNK_IT)      // 512 float4 per warp-chunk

__device__ float g_partials[NBLOCKS];
__device__ unsigned int g_count = 0;    // always 0 at kernel entry
__device__ unsigned int g_work  = 0;    // always 0 at kernel entry

__device__ __forceinline__ float block_reduce(float acc, float* warp_sums)
{
    #pragma unroll
    for (int off = 16; off > 0; off >>= 1)
        acc += __shfl_down_sync(0xFFFFFFFFu, acc, off);
    int lane = threadIdx.x & 31;
    int wid  = threadIdx.x >> 5;
    if (lane == 0) warp_sums[wid] = acc;
    __syncthreads();
    float v = 0.0f;
    if (wid == 0) {
        v = (lane < NTHREADS / 32) ? warp_sums[lane] : 0.0f;
        #pragma unroll
        for (int off = 16; off > 0; off >>= 1)
            v += __shfl_down_sync(0xFFFFFFFFu, v, off);
    }
    return v;   // valid in warp 0 lane 0
}

__device__ __forceinline__ float bce1(float x, int t)
{
    // t in {0,1}: y = t ? -x : x via sign-bit XOR
    float y = __int_as_float(__float_as_int(x) ^ (t << 31));
    return fmaxf(y, 0.0f) + __logf(1.0f + __expf(-fabsf(y)));
}

__device__ __forceinline__ float bce4(float4 xv, int4 tv)
{
    float s0 = bce1(xv.x, tv.x);
    float s1 = bce1(xv.y, tv.y);
    float s2 = bce1(xv.z, tv.z);
    float s3 = bce1(xv.w, tv.w);
    return (s0 + s1) + (s2 + s3);
}

__global__ __launch_bounds__(NTHREADS) void bce_warp_dyn_kernel(
    const float* __restrict__ x, const int* __restrict__ t,
    float* __restrict__ out, long long n4, float inv_n, int nchunks)
{
    const float4* __restrict__ x4 = (const float4*)x;
    const int4*   __restrict__ t4 = (const int4*)t;

    const int lane = threadIdx.x & 31;
    float acc = 0.0f;

    // ---- per-warp dynamic chunk loop (no block barriers) ----
    int chunk = 0;
    if (lane == 0) chunk = (int)atomicAdd(&g_work, 1u);
    chunk = __shfl_sync(0xFFFFFFFFu, chunk, 0);

    while (chunk < nchunks) {
        int next = 0;
        if (lane == 0) next = (int)atomicAdd(&g_work, 1u);   // prefetch grab

        long long base = (long long)chunk * WCHUNK + lane;
        #pragma unroll 1
        for (int j = 0; j < WCHUNK_IT; j++) {
            long long i = base + (long long)j * 32;
            float4 xv = __ldcs(&x4[i]);
            int4   tv = __ldcs(&t4[i]);
            acc += bce4(xv, tv);
        }

        chunk = __shfl_sync(0xFFFFFFFFu, next, 0);
    }

    // ---- tail (n4 not divisible by WCHUNK; empty for 64M inputs) ----
    long long tail_start = (long long)nchunks * WCHUNK;
    for (long long i = tail_start + (long long)blockIdx.x * blockDim.x + threadIdx.x;
         i < n4; i += (long long)gridDim.x * blockDim.x) {
        acc += bce4(__ldcs(&x4[i]), __ldcs(&t4[i]));
    }

    // ---- block + grid reduction ----
    __shared__ float warp_sums[NTHREADS / 32];
    float bsum = block_reduce(acc, warp_sums);

    __shared__ bool is_last;
    if (threadIdx.x == 0) {
        g_partials[blockIdx.x] = bsum;
        __threadfence();
        unsigned int done = atomicAdd(&g_count, 1u);
        is_last = (done == (unsigned int)(gridDim.x - 1));
    }
    __syncthreads();

    if (is_last) {
        float a2 = 0.0f;
        for (int k = threadIdx.x; k < NBLOCKS; k += NTHREADS)
            a2 += g_partials[k];
        __syncthreads();
        float total = block_reduce(a2, warp_sums);
        if (threadIdx.x == 0) {
            out[0] = total * inv_n;
            g_count = 0;          // reset for next graph replay
            g_work  = 0;
        }
    }
}

extern "C" void kernel_launch(void* const* d_in, const int* in_sizes, int n_in,
                              void* d_out, int out_size)
{
    const float* x = (const float*)d_in[0];
    const int*   t = (const int*)d_in[1];
    float* out = (float*)d_out;

    long long n  = (long long)in_sizes[0];   // 64M
    long long n4 = n >> 2;
    int nchunks  = (int)(n4 / WCHUNK);       // 32768 for 64M (exact)

    bce_warp_dyn_kernel<<<NBLOCKS, NTHREADS>>>(x, t, out, n4,
                                               1.0f / (float)n, nchunks);
}

// round 6
// speedup vs baseline: 1.4078x; 1.4078x over previous
#include <cuda_runtime.h>
#include <cuda_bf16.h>
#include <cstdint>

// BCE-with-logits mean over 8192x8192, single kernel.
// Block-level dynamic chunk scheduling (compact chip-wide footprint:
// all warps of a CTA stream one contiguous chunk together).
// Double-buffered chunk index -> ONE barrier per chunk.
// Last-block-done final reduction; counters self-reset for graph replay.

#define NBLOCKS   1184          // 148 SMs * 8 CTAs (one full wave)
#define NTHREADS  256
#define CHUNK_IT  4
#define CHUNK     (NTHREADS * CHUNK_IT)   // 1024 float4 per chunk (16KB x + 16KB t)

__device__ float g_partials[NBLOCKS];
__device__ unsigned int g_count = 0;    // always 0 at kernel entry
__device__ unsigned int g_work  = 0;    // always 0 at kernel entry

__device__ __forceinline__ float block_reduce(float acc, float* warp_sums)
{
    #pragma unroll
    for (int off = 16; off > 0; off >>= 1)
        acc += __shfl_down_sync(0xFFFFFFFFu, acc, off);
    int lane = threadIdx.x & 31;
    int wid  = threadIdx.x >> 5;
    if (lane == 0) warp_sums[wid] = acc;
    __syncthreads();
    float v = 0.0f;
    if (wid == 0) {
        v = (lane < NTHREADS / 32) ? warp_sums[lane] : 0.0f;
        #pragma unroll
        for (int off = 16; off > 0; off >>= 1)
            v += __shfl_down_sync(0xFFFFFFFFu, v, off);
    }
    return v;   // valid in warp 0 lane 0
}

__device__ __forceinline__ float bce1(float x, int t)
{
    // t in {0,1}: y = t ? -x : x via sign-bit XOR
    float y = __int_as_float(__float_as_int(x) ^ (t << 31));
    return fmaxf(y, 0.0f) + __logf(1.0f + __expf(-fabsf(y)));
}

__device__ __forceinline__ float bce4(float4 xv, int4 tv)
{
    float s0 = bce1(xv.x, tv.x);
    float s1 = bce1(xv.y, tv.y);
    float s2 = bce1(xv.z, tv.z);
    float s3 = bce1(xv.w, tv.w);
    return (s0 + s1) + (s2 + s3);
}

__global__ __launch_bounds__(NTHREADS) void bce_dyn2_kernel(
    const float* __restrict__ x, const int* __restrict__ t,
    float* __restrict__ out, long long n4, float inv_n, int nchunks)
{
    const float4* __restrict__ x4 = (const float4*)x;
    const int4*   __restrict__ t4 = (const int4*)t;

    __shared__ int   s_chunk[2];
    __shared__ float warp_sums[NTHREADS / 32];

    float acc = 0.0f;

    if (threadIdx.x == 0) s_chunk[0] = (int)atomicAdd(&g_work, 1u);
    __syncthreads();
    int parity = 0;
    int chunk  = s_chunk[0];

    while (chunk < nchunks) {
        // prefetch next chunk index into the other slot
        if (threadIdx.x == 0) s_chunk[parity ^ 1] = (int)atomicAdd(&g_work, 1u);

        long long base = (long long)chunk * CHUNK + threadIdx.x;
        #pragma unroll 1
        for (int j = 0; j < CHUNK_IT; j++) {
            long long i = base + j * NTHREADS;
            float4 xv = __ldcs(&x4[i]);
            int4   tv = __ldcs(&t4[i]);
            acc += bce4(xv, tv);
        }

        __syncthreads();         // publishes slot parity^1; protects slot parity
        parity ^= 1;
        chunk = s_chunk[parity];
    }

    // ---- generic tail (empty for 64M inputs: 16M/1024 = 16384 exact) ----
    long long tail_start = (long long)nchunks * CHUNK;
    for (long long i = tail_start + (long long)blockIdx.x * blockDim.x + threadIdx.x;
         i < n4; i += (long long)gridDim.x * blockDim.x) {
        acc += bce4(__ldcs(&x4[i]), __ldcs(&t4[i]));
    }

    // ---- block + grid reduction ----
    float bsum = block_reduce(acc, warp_sums);

    __shared__ bool is_last;
    if (threadIdx.x == 0) {
        g_partials[blockIdx.x] = bsum;
        __threadfence();
        unsigned int done = atomicAdd(&g_count, 1u);
        is_last = (done == (unsigned int)(gridDim.x - 1));
    }
    __syncthreads();

    if (is_last) {
        float a2 = 0.0f;
        for (int k = threadIdx.x; k < NBLOCKS; k += NTHREADS)
            a2 += g_partials[k];
        __syncthreads();
        float total = block_reduce(a2, warp_sums);
        if (threadIdx.x == 0) {
            out[0] = total * inv_n;
            g_count = 0;          // reset for next graph replay
            g_work  = 0;
        }
    }
}

extern "C" void kernel_launch(void* const* d_in, const int* in_sizes, int n_in,
                              void* d_out, int out_size)
{
    const float* x = (const float*)d_in[0];
    const int*   t = (const int*)d_in[1];
    float* out = (float*)d_out;

    long long n  = (long long)in_sizes[0];   // 64M
    long long n4 = n >> 2;
    int nchunks  = (int)(n4 / CHUNK);        // 16384 for 64M (exact)

    bce_dyn2_kernel<<<NBLOCKS, NTHREADS>>>(x, t, out, n4,
                                           1.0f / (float)n, nchunks);
}